// round 2
// baseline (speedup 1.0000x reference)
#include <cuda_runtime.h>
#include <cuda_bf16.h>
#include <stdint.h>

#define HDIM   256
#define BATCH  32
#define TSTEPS 4096
#define EDGES  8192
#define D2     512
#define MTOT   (TSTEPS * BATCH)   // 131072

// ---------------- scratch (static device globals; no runtime alloc) ----------------
__device__ __align__(16) float          g_p[BATCH * D2];    // W1*hidden + b_attn  [b][d]
__device__ __align__(16) __nv_bfloat16  g_W2b[D2 * HDIM];   // bf16(W_attn[:, 256:512]) [n][k]
__device__ __align__(16) float          g_sc[MTOT];         // scores -> weights  [t*32 + b]

__device__ __forceinline__ uint32_t smem_u32(const void* p) {
    uint32_t a;
    asm("{ .reg .u64 t; cvta.to.shared.u64 t, %1; cvt.u32.u64 %0, t; }" : "=r"(a) : "l"(p));
    return a;
}
__device__ __forceinline__ float tanh_fast(float x) {
    float t;
    asm("tanh.approx.f32 %0, %1;" : "=f"(t) : "f"(x));
    return t;
}

// ---------------- kernel 1: p = W1*hidden + b_attn ; W2 -> bf16 ----------------
__global__ void prep_kernel(const float* __restrict__ hidden,
                            const float* __restrict__ W,
                            const float* __restrict__ ba) {
    int idx = blockIdx.x * 256 + threadIdx.x;       // 64 blocks x 256 = 16384
    int b = idx >> 9;
    int d = idx & 511;
    const float* wr = W + (size_t)d * 512;          // W_attn row d, cols 0..255 = W1
    const float* hr = hidden + b * HDIM;
    float s = ba[d];
    #pragma unroll 4
    for (int k = 0; k < HDIM; k++) s += hr[k] * wr[k];
    g_p[idx] = s;                                    // idx == b*512 + d

    for (int i = idx; i < D2 * HDIM; i += 16384) {   // W2 = W_attn[:, 256:512] -> bf16
        int n = i >> 8, k = i & 255;
        g_W2b[i] = __float2bfloat16(W[(size_t)n * 512 + HDIM + k]);
    }
}

// ---------------- kernel 2: mma.sync bf16 GEMM + fused tanh / v-dot ----------------
// CTA: 256 rows (M), loop over 8 N-chunks of 64. 8 warps, warp tile 32(M) x 64(N).
// Smem layout (bytes):
static constexpr int SM_A     = 0;        // 256 rows x 512 B (bf16 k=256, swizzled) = 131072
static constexpr int SM_B     = 131072;   // 64 rows x 512 B = 32768
static constexpr int SM_P     = 163840;   // 32 x 65 floats   = 8320
static constexpr int SM_V     = 172288;   // 512 floats       = 2048
static constexpr int SM_TOTAL = 174336;

// swizzled byte offset within a tile: row * 512 + ((k16 ^ (row&7)) << 4), k16 in [0,32)

__global__ __launch_bounds__(256, 1)
void attn_gemm_kernel(const float* __restrict__ enc, const float* __restrict__ v) {
    extern __shared__ char smem[];
    uint32_t sb = smem_u32(smem);
    int tid = threadIdx.x, wid = tid >> 5, lid = tid & 31;
    int gid = lid >> 2, tg = lid & 3;

    // ---- A: enc rows [blk*256, blk*256+256) : fp32 -> bf16, swizzled smem ----
    const float4* asrc = (const float4*)(enc + (size_t)blockIdx.x * 256 * HDIM);
    for (int i = tid; i < 8192; i += 256) {
        int row = i >> 5, k16 = i & 31;
        float4 a = asrc[row * 64 + k16 * 2];
        float4 b = asrc[row * 64 + k16 * 2 + 1];
        __nv_bfloat162 t0 = __floats2bfloat162_rn(a.x, a.y);
        __nv_bfloat162 t1 = __floats2bfloat162_rn(a.z, a.w);
        __nv_bfloat162 t2 = __floats2bfloat162_rn(b.x, b.y);
        __nv_bfloat162 t3 = __floats2bfloat162_rn(b.z, b.w);
        uint4 val;
        val.x = *reinterpret_cast<uint32_t*>(&t0);
        val.y = *reinterpret_cast<uint32_t*>(&t1);
        val.z = *reinterpret_cast<uint32_t*>(&t2);
        val.w = *reinterpret_cast<uint32_t*>(&t3);
        *reinterpret_cast<uint4*>(smem + SM_A + row * 512 + ((k16 ^ (row & 7)) << 4)) = val;
    }
    float* v_s = (float*)(smem + SM_V);
    for (int i = tid; i < D2; i += 256) v_s[i] = v[i];
    float* p_s = (float*)(smem + SM_P);

    // ---- per-lane ldmatrix addresses ----
    // A x4: lane l -> row = R + (l&7) + (l&8), k-half = (l>>4)&1
    int arow = wid * 32 + (lid & 7) + (lid & 8);
    uint32_t aoff0 = sb + SM_A + arow * 512;
    uint32_t aoff1 = aoff0 + 16 * 512;          // rows +16 (same row&7 -> same swizzle)
    uint32_t asw   = (uint32_t)(arow & 7);
    uint32_t ahalf = (lid >> 4) & 1;
    // B x4 #t: lane l -> n = (l&7) + ((l>>4)&1)*8 + t*16, k-half = (l>>3)&1
    int bn = (lid & 7) + (((lid >> 4) & 1) << 3);
    uint32_t boff  = sb + SM_B + bn * 512;
    uint32_t bsw   = (uint32_t)(bn & 7);
    uint32_t bhalf = (lid >> 3) & 1;

    float rs[2][2] = {{0.f, 0.f}, {0.f, 0.f}};   // row partial sums: [mfrag][rowhalf]

    for (int c = 0; c < 8; c++) {
        __syncthreads();   // previous chunk's ldmatrix / p_s readers done
        // B chunk: W2b rows [c*64, c*64+64), bf16 -> swizzled smem
        const uint4* bsrc = (const uint4*)(g_W2b + (size_t)c * 64 * HDIM);
        for (int i = tid; i < 2048; i += 256) {
            int row = i >> 5, k16 = i & 31;
            *reinterpret_cast<uint4*>(smem + SM_B + row * 512 + ((k16 ^ (row & 7)) << 4))
                = bsrc[row * 32 + k16];
        }
        // p chunk [32 x 64], padded stride 65
        for (int i = tid; i < 2048; i += 256) {
            int pb = i >> 6, j = i & 63;
            p_s[pb * 65 + j] = g_p[pb * D2 + c * 64 + j];
        }
        __syncthreads();

        float acc[2][8][4];
        #pragma unroll
        for (int i = 0; i < 2; i++)
            #pragma unroll
            for (int j = 0; j < 8; j++)
                #pragma unroll
                for (int r = 0; r < 4; r++) acc[i][j][r] = 0.f;

        #pragma unroll
        for (int kk = 0; kk < 16; kk++) {
            uint32_t ak = (((2u * kk + ahalf) ^ asw) << 4);
            uint32_t bk = (((2u * kk + bhalf) ^ bsw) << 4);
            uint32_t a0[4], a1[4], br[16];
            asm volatile("ldmatrix.sync.aligned.m8n8.x4.shared.b16 {%0,%1,%2,%3}, [%4];"
                : "=r"(a0[0]), "=r"(a0[1]), "=r"(a0[2]), "=r"(a0[3]) : "r"(aoff0 + ak));
            asm volatile("ldmatrix.sync.aligned.m8n8.x4.shared.b16 {%0,%1,%2,%3}, [%4];"
                : "=r"(a1[0]), "=r"(a1[1]), "=r"(a1[2]), "=r"(a1[3]) : "r"(aoff1 + ak));
            #pragma unroll
            for (int t = 0; t < 4; t++) {
                asm volatile("ldmatrix.sync.aligned.m8n8.x4.shared.b16 {%0,%1,%2,%3}, [%4];"
                    : "=r"(br[4 * t]), "=r"(br[4 * t + 1]),
                      "=r"(br[4 * t + 2]), "=r"(br[4 * t + 3])
                    : "r"(boff + (uint32_t)t * 8192 + bk));
            }
            #pragma unroll
            for (int j = 0; j < 8; j++) {
                asm volatile(
                    "mma.sync.aligned.m16n8k16.row.col.f32.bf16.bf16.f32 "
                    "{%0,%1,%2,%3}, {%4,%5,%6,%7}, {%8,%9}, {%0,%1,%2,%3};"
                    : "+f"(acc[0][j][0]), "+f"(acc[0][j][1]),
                      "+f"(acc[0][j][2]), "+f"(acc[0][j][3])
                    : "r"(a0[0]), "r"(a0[1]), "r"(a0[2]), "r"(a0[3]),
                      "r"(br[2 * j]), "r"(br[2 * j + 1]));
                asm volatile(
                    "mma.sync.aligned.m16n8k16.row.col.f32.bf16.bf16.f32 "
                    "{%0,%1,%2,%3}, {%4,%5,%6,%7}, {%8,%9}, {%0,%1,%2,%3};"
                    : "+f"(acc[1][j][0]), "+f"(acc[1][j][1]),
                      "+f"(acc[1][j][2]), "+f"(acc[1][j][3])
                    : "r"(a1[0]), "r"(a1[1]), "r"(a1[2]), "r"(a1[3]),
                      "r"(br[2 * j]), "r"(br[2 * j + 1]));
            }
        }

        // Fused epilogue: acc(row,col) -> += v[col] * tanh(acc + p[b, col])
        const float* vc = v_s + c * 64;
        #pragma unroll
        for (int i = 0; i < 2; i++) {
            #pragma unroll
            for (int r = 0; r < 4; r++) {
                int bix = i * 16 + gid + ((r >> 1) << 3);   // row & 31
                const float* pr = p_s + bix * 65;
                float s = 0.f;
                #pragma unroll
                for (int j = 0; j < 8; j++) {
                    int lcol = j * 8 + tg * 2 + (r & 1);
                    float x = acc[i][j][r] + pr[lcol];
                    s += vc[lcol] * tanh_fast(x);
                }
                rs[i][r >> 1] += s;
            }
        }
    }

    // quad reduction (lanes share gid, differ in tg)
    #pragma unroll
    for (int i = 0; i < 2; i++)
        #pragma unroll
        for (int h = 0; h < 2; h++) {
            float x = rs[i][h];
            x += __shfl_xor_sync(0xFFFFFFFF, x, 1);
            x += __shfl_xor_sync(0xFFFFFFFF, x, 2);
            rs[i][h] = x;
        }
    if (tg == 0) {
        int base = blockIdx.x * 256 + wid * 32;
        g_sc[base + gid]          = rs[0][0];
        g_sc[base + gid + 8]      = rs[0][1];
        g_sc[base + 16 + gid]     = rs[1][0];
        g_sc[base + 16 + gid + 8] = rs[1][1];
    }
}

// ---------------- kernel 3: softmax over T per batch; zero d_out ----------------
__global__ void softmax_zero_kernel(float* __restrict__ out) {
    int b = blockIdx.x, tid = threadIdx.x;
    __shared__ float red[256];
    float mx = -1e30f;
    for (int t = tid; t < TSTEPS; t += 256) mx = fmaxf(mx, g_sc[t * 32 + b]);
    red[tid] = mx; __syncthreads();
    for (int s = 128; s > 0; s >>= 1) { if (tid < s) red[tid] = fmaxf(red[tid], red[tid + s]); __syncthreads(); }
    float m0 = red[0]; __syncthreads();
    float sum = 0.0f;
    for (int t = tid; t < TSTEPS; t += 256) {
        float e = __expf(g_sc[t * 32 + b] - m0);
        g_sc[t * 32 + b] = e;
        sum += e;
    }
    red[tid] = sum; __syncthreads();
    for (int s = 128; s > 0; s >>= 1) { if (tid < s) red[tid] += red[tid + s]; __syncthreads(); }
    float inv = 1.0f / red[0];
    for (int t = tid; t < TSTEPS; t += 256) {
        g_sc[t * 32 + b] *= inv;
        out[b * TSTEPS + t] = 0.0f;
    }
}

// ---------------- kernel 4: masked edge scatter-add, x0.1 folded in ----------------
__global__ void scatter_kernel(const int* __restrict__ esrc,
                               const int* __restrict__ edst,
                               float* __restrict__ out) {
    int i = blockIdx.x * 256 + threadIdx.x;
    if (i >= BATCH * EDGES) return;
    int b = i >> 13;                    // EDGES = 8192
    int s = esrc[i], d = edst[i];
    if (d != s + 1) {
        atomicAdd(out + b * TSTEPS + d, 0.1f * g_sc[s * 32 + b]);
    }
}

// ---------------- host launch ----------------
extern "C" void kernel_launch(void* const* d_in, const int* in_sizes, int n_in,
                              void* d_out, int out_size) {
    const float* hidden = (const float*)d_in[0];
    const float* enc    = (const float*)d_in[1];
    const int*   esrc   = (const int*)d_in[2];
    const int*   edst   = (const int*)d_in[3];
    const float* W      = (const float*)d_in[4];
    const float* ba     = (const float*)d_in[5];
    const float* v      = (const float*)d_in[6];
    float* out = (float*)d_out;

    cudaFuncSetAttribute(attn_gemm_kernel,
                         cudaFuncAttributeMaxDynamicSharedMemorySize, SM_TOTAL);

    prep_kernel<<<64, 256>>>(hidden, W, ba);
    attn_gemm_kernel<<<MTOT / 256, 256, SM_TOTAL>>>(enc, v);
    softmax_zero_kernel<<<BATCH, 256>>>(out);
    scatter_kernel<<<(BATCH * EDGES + 255) / 256, 256>>>(esrc, edst, out);
}

// round 3
// speedup vs baseline: 1.5266x; 1.5266x over previous
#include <cuda_runtime.h>
#include <cuda_bf16.h>
#include <stdint.h>

#define HDIM   256
#define BATCH  32
#define TSTEPS 4096
#define EDGES  8192
#define D2     512
#define MTOT   (TSTEPS * BATCH)   // 131072

// ---------------- scratch (static device globals; no runtime alloc) ----------------
__device__ __align__(16) float          g_p[BATCH * D2];    // W1*hidden + b_attn  [b][d]
__device__ __align__(16) __nv_bfloat16  g_W2b[D2 * HDIM];   // bf16(W_attn[:,256:512]) [n][k]
__device__ __align__(16) float          g_e[MTOT];          // exp(score)  [t*32 + b]
__device__ __align__(16) float          g_sum[BATCH];       // per-batch softmax denom

__device__ __forceinline__ uint32_t smem_u32(const void* p) {
    uint32_t a;
    asm("{ .reg .u64 t; cvta.to.shared.u64 t, %1; cvt.u32.u64 %0, t; }" : "=r"(a) : "l"(p));
    return a;
}
__device__ __forceinline__ float tanh_fast(float x) {
    float t;
    asm("tanh.approx.f32 %0, %1;" : "=f"(t) : "f"(x));
    return t;
}
__device__ __forceinline__ void cp_async16(uint32_t dst, const void* src) {
    asm volatile("cp.async.ca.shared.global [%0], [%1], 16;" :: "r"(dst), "l"(src));
}
#define CP_COMMIT() asm volatile("cp.async.commit_group;" ::: "memory")
#define CP_WAIT0()  asm volatile("cp.async.wait_group 0;" ::: "memory")

// ---------------- kernel 1: p = W1*hidden + b_attn (warp-per-output, coalesced);
//                  W2 -> bf16 ; zero d_out and g_sum ----------------
__global__ void prep_kernel(const float* __restrict__ hidden,
                            const float* __restrict__ W,
                            const float* __restrict__ ba,
                            float* __restrict__ out) {
    int tid = threadIdx.x, lid = tid & 31;
    int gw = blockIdx.x * 8 + (tid >> 5);        // 2048 blocks x 8 warps = 16384 outputs
    int b = gw >> 9, d = gw & 511;
    const float* wr = W + (size_t)d * 512;       // W1 = W_attn[:, 0:256]
    const float* hr = hidden + b * HDIM;
    float s = 0.f;
    #pragma unroll
    for (int k = lid; k < HDIM; k += 32) s += wr[k] * hr[k];
    #pragma unroll
    for (int o = 16; o > 0; o >>= 1) s += __shfl_xor_sync(0xFFFFFFFF, s, o);
    if (lid == 0) g_p[gw] = s + ba[d];           // gw == b*512 + d

    int gt = blockIdx.x * 256 + tid;             // 524288 threads
    if (gt < D2 * HDIM) {                        // 131072: W2 -> bf16
        int n = gt >> 8, k = gt & 255;
        g_W2b[gt] = __float2bfloat16(W[(size_t)n * 512 + HDIM + k]);
    }
    if (gt < MTOT) out[gt] = 0.f;                // zero output (poisoned by harness)
    if (gt < BATCH) g_sum[gt] = 0.f;
}

// ---------------- kernel 2: mma.sync bf16 GEMM, fused tanh/v-dot/exp epilogue ----------------
// CTA: 128 M-rows, 8 warps (warp tile 16x64), 8 N-chunks of 64, occupancy 2.
static constexpr int SM_A     = 0;        // 128 rows x 512 B (bf16 k=256, swizzled) = 65536
static constexpr int SM_B     = 65536;    // 64 rows x 512 B                         = 32768
static constexpr int SM_P     = 98304;    // 32 x 68 floats (16B-aligned stride)     = 8704
static constexpr int SM_V     = 107008;   // 512 floats                              = 2048
static constexpr int SM_BS    = 109056;   // 32 floats per-b partial sums            = 128
static constexpr int SM_TOTAL = 109184;

__global__ __launch_bounds__(256, 2)
void attn_gemm_kernel(const float* __restrict__ enc, const float* __restrict__ v) {
    extern __shared__ char smem[];
    uint32_t sb = smem_u32(smem);
    int tid = threadIdx.x, wid = tid >> 5, lid = tid & 31;
    int gid = lid >> 2, tg = lid & 3;

    float* p_s  = (float*)(smem + SM_P);
    float* v_s  = (float*)(smem + SM_V);
    float* bsum = (float*)(smem + SM_BS);
    if (tid < 32) bsum[tid] = 0.f;

    // ---- prologue: async-load B chunk 0 + p chunk 0 + v ----
    {
        const char* bsrc = (const char*)g_W2b;
        for (int i = tid; i < 2048; i += 256) {
            int row = i >> 5, k16 = i & 31;
            cp_async16(sb + SM_B + row * 512 + ((k16 ^ (row & 7)) << 4), bsrc + i * 16);
        }
        for (int i = tid; i < 512; i += 256) {
            int pb = i >> 4, j16 = i & 15;
            cp_async16(sb + SM_P + pb * 272 + j16 * 16, (const char*)(g_p + pb * 512 + j16 * 4));
        }
        if (tid < 128)
            cp_async16(sb + SM_V + tid * 16, (const char*)(v + tid * 4));
        CP_COMMIT();
    }

    // ---- A: enc rows [blk*128, +128): fp32 -> bf16, swizzled smem ----
    const float4* asrc = (const float4*)(enc + (size_t)blockIdx.x * 128 * HDIM);
    for (int i = tid; i < 4096; i += 256) {
        int row = i >> 5, k16 = i & 31;
        float4 a = asrc[row * 64 + k16 * 2];
        float4 b = asrc[row * 64 + k16 * 2 + 1];
        __nv_bfloat162 t0 = __floats2bfloat162_rn(a.x, a.y);
        __nv_bfloat162 t1 = __floats2bfloat162_rn(a.z, a.w);
        __nv_bfloat162 t2 = __floats2bfloat162_rn(b.x, b.y);
        __nv_bfloat162 t3 = __floats2bfloat162_rn(b.z, b.w);
        uint4 val;
        val.x = *reinterpret_cast<uint32_t*>(&t0);
        val.y = *reinterpret_cast<uint32_t*>(&t1);
        val.z = *reinterpret_cast<uint32_t*>(&t2);
        val.w = *reinterpret_cast<uint32_t*>(&t3);
        *reinterpret_cast<uint4*>(smem + SM_A + row * 512 + ((k16 ^ (row & 7)) << 4)) = val;
    }

    // ---- per-lane ldmatrix addresses (layout validated in R2) ----
    int arow = wid * 16 + (lid & 7) + (lid & 8);
    uint32_t aoff = sb + SM_A + arow * 512;
    uint32_t asw  = (uint32_t)(arow & 7);
    uint32_t ahalf = (lid >> 4) & 1;
    int bn = (lid & 7) + (((lid >> 4) & 1) << 3);
    uint32_t boff = sb + SM_B + bn * 512;
    uint32_t bsw  = (uint32_t)(bn & 7);
    uint32_t bhalf = (lid >> 3) & 1;

    float rs[2] = {0.f, 0.f};   // partial scores for rows (gid) and (gid+8)

    for (int c = 0; c < 8; c++) {
        if (c > 0) {
            __syncthreads();    // previous chunk's B/p consumers done
            const char* bsrc = (const char*)(g_W2b + (size_t)c * 64 * HDIM);
            for (int i = tid; i < 2048; i += 256) {
                int row = i >> 5, k16 = i & 31;
                cp_async16(sb + SM_B + row * 512 + ((k16 ^ (row & 7)) << 4), bsrc + i * 16);
            }
            for (int i = tid; i < 512; i += 256) {
                int pb = i >> 4, j16 = i & 15;
                cp_async16(sb + SM_P + pb * 272 + j16 * 16,
                           (const char*)(g_p + pb * 512 + c * 64 + j16 * 4));
            }
            CP_COMMIT();
        }
        CP_WAIT0();
        __syncthreads();        // B/p/v (and A stores on c==0) visible

        float acc[8][4];
        #pragma unroll
        for (int j = 0; j < 8; j++)
            #pragma unroll
            for (int r = 0; r < 4; r++) acc[j][r] = 0.f;

        #pragma unroll
        for (int kk = 0; kk < 16; kk++) {
            uint32_t ak = (((2u * kk + ahalf) ^ asw) << 4);
            uint32_t bk = (((2u * kk + bhalf) ^ bsw) << 4);
            uint32_t a[4], br[16];
            asm volatile("ldmatrix.sync.aligned.m8n8.x4.shared.b16 {%0,%1,%2,%3}, [%4];"
                : "=r"(a[0]), "=r"(a[1]), "=r"(a[2]), "=r"(a[3]) : "r"(aoff + ak));
            #pragma unroll
            for (int t = 0; t < 4; t++) {
                asm volatile("ldmatrix.sync.aligned.m8n8.x4.shared.b16 {%0,%1,%2,%3}, [%4];"
                    : "=r"(br[4 * t]), "=r"(br[4 * t + 1]),
                      "=r"(br[4 * t + 2]), "=r"(br[4 * t + 3])
                    : "r"(boff + (uint32_t)t * 8192 + bk));
            }
            #pragma unroll
            for (int j = 0; j < 8; j++) {
                asm volatile(
                    "mma.sync.aligned.m16n8k16.row.col.f32.bf16.bf16.f32 "
                    "{%0,%1,%2,%3}, {%4,%5,%6,%7}, {%8,%9}, {%0,%1,%2,%3};"
                    : "+f"(acc[j][0]), "+f"(acc[j][1]), "+f"(acc[j][2]), "+f"(acc[j][3])
                    : "r"(a[0]), "r"(a[1]), "r"(a[2]), "r"(a[3]),
                      "r"(br[2 * j]), "r"(br[2 * j + 1]));
            }
        }

        // ---- fused epilogue: += v[col] * tanh(acc + p[b][col]) ----
        const float* vc = v_s + c * 64;
        #pragma unroll
        for (int r = 0; r < 4; r++) {
            int rh = r >> 1;
            int bix = (wid * 16 + gid + (rh << 3)) & 31;
            const float* pr = p_s + bix * 68;
            float s = 0.f;
            #pragma unroll
            for (int j = 0; j < 8; j++) {
                int lcol = j * 8 + tg * 2 + (r & 1);
                s += vc[lcol] * tanh_fast(acc[j][r] + pr[lcol]);
            }
            rs[rh] += s;
        }
    }

    // quad reduction (lanes share gid, differ in tg)
    #pragma unroll
    for (int h = 0; h < 2; h++) {
        float x = rs[h];
        x += __shfl_xor_sync(0xFFFFFFFF, x, 1);
        x += __shfl_xor_sync(0xFFFFFFFF, x, 2);
        rs[h] = x;
    }
    if (tg == 0) {
        int m = blockIdx.x * 128 + wid * 16 + gid;
        float e0 = __expf(rs[0]);
        float e1 = __expf(rs[1]);
        g_e[m]     = e0;
        g_e[m + 8] = e1;
        atomicAdd(&bsum[m & 31], e0);
        atomicAdd(&bsum[(m + 8) & 31], e1);
    }
    __syncthreads();
    if (tid < 32) atomicAdd(&g_sum[tid], bsum[tid]);
}

// ---------------- kernel 3: masked edge scatter-add with softmax divide, x0.1 ----------------
__global__ void scatter_kernel(const int* __restrict__ esrc,
                               const int* __restrict__ edst,
                               float* __restrict__ out) {
    int i = blockIdx.x * 256 + threadIdx.x;
    if (i >= BATCH * EDGES) return;
    int b = i >> 13;                    // EDGES = 8192
    int s = esrc[i], d = edst[i];
    if (d != s + 1) {
        float w = 0.1f * g_e[s * 32 + b] / g_sum[b];
        atomicAdd(out + b * TSTEPS + d, w);
    }
}

// ---------------- host launch ----------------
extern "C" void kernel_launch(void* const* d_in, const int* in_sizes, int n_in,
                              void* d_out, int out_size) {
    const float* hidden = (const float*)d_in[0];
    const float* enc    = (const float*)d_in[1];
    const int*   esrc   = (const int*)d_in[2];
    const int*   edst   = (const int*)d_in[3];
    const float* W      = (const float*)d_in[4];
    const float* ba     = (const float*)d_in[5];
    const float* v      = (const float*)d_in[6];
    float* out = (float*)d_out;

    cudaFuncSetAttribute(attn_gemm_kernel,
                         cudaFuncAttributeMaxDynamicSharedMemorySize, SM_TOTAL);

    prep_kernel<<<2048, 256>>>(hidden, W, ba, out);
    attn_gemm_kernel<<<MTOT / 128, 256, SM_TOTAL>>>(enc, v);
    scatter_kernel<<<(BATCH * EDGES + 255) / 256, 256>>>(esrc, edst, out);
}